// round 2
// baseline (speedup 1.0000x reference)
#include <cuda_runtime.h>
#include <math.h>

#define N_CELLS 20
#define IN 8
#define HID 10
#define NGATES 800   // 20 cells * 40 gate rows
#define FEAT 200
#define H1 50
#define H2 10

__device__ __forceinline__ float sigmoidf_(float x) {
    return 1.0f / (1.0f + expf(-x));
}

__global__ __launch_bounds__(800, 1)
void lstm_mlp_fused(const float* __restrict__ x,
                    const float* __restrict__ h0,
                    const float* __restrict__ c0,
                    const float* __restrict__ W_ih,
                    const float* __restrict__ W_hh,
                    const float* __restrict__ b_ih,
                    const float* __restrict__ b_hh,
                    const float* __restrict__ W1,
                    const float* __restrict__ b1,
                    const float* __restrict__ W2,
                    const float* __restrict__ b2,
                    const float* __restrict__ W3,
                    const float* __restrict__ b3,
                    float* __restrict__ out)
{
    __shared__ float s_x[IN];
    __shared__ float s_gates[NGATES];
    __shared__ float s_feat[FEAT];
    __shared__ float s_h1[H1];
    __shared__ float s_h2[H2];

    const int t = threadIdx.x;

    if (t < IN) s_x[t] = x[t];
    __syncthreads();

    // ---- Stage 1: gates[k][g] = W_ih[k,g,:]·x + W_hh[k,g,:]·h0[k,:] + b_ih + b_hh
    if (t < NGATES) {
        const int cell = t / 40;
        float acc = b_ih[t] + b_hh[t];
        const float* wih = W_ih + t * IN;
        #pragma unroll
        for (int i = 0; i < IN; ++i) acc = fmaf(wih[i], s_x[i], acc);
        const float* whh = W_hh + t * HID;
        const float* hrow = h0 + cell * HID;
        #pragma unroll
        for (int j = 0; j < HID; ++j) acc = fmaf(whh[j], hrow[j], acc);
        s_gates[t] = acc;
    }
    __syncthreads();

    // ---- Stage 2: LSTM cell update + feature reorder (gen cells first, then opp)
    if (t < FEAT) {
        const int cell = t / HID;
        const int j = t % HID;
        const float* g = s_gates + cell * 40;
        float ig = sigmoidf_(g[j]);
        float fg = sigmoidf_(g[10 + j]);
        float gg = tanhf(g[20 + j]);
        float og = sigmoidf_(g[30 + j]);
        float c = fg * c0[t] + ig * gg;
        float h = og * tanhf(c);
        int fidx = (cell >= 10) ? (cell - 10) * HID + j : 100 + cell * HID + j;
        s_feat[fidx] = h;
    }
    __syncthreads();

    // ---- Stage 3: h1 = tanh(W1 @ feat + b1)   (50 outputs, 8 lanes each)
    // Warp-uniform guard: warps 0..12 fully active (t < 416) so the
    // full-mask shuffles are legal; rows 50/51 are clamped & discarded.
    if (t < 416) {
        const int row_raw = t >> 3;
        const int row = (row_raw < H1) ? row_raw : (H1 - 1);  // clamp: no OOB reads
        const int lane = t & 7;
        const float* w = W1 + row * FEAT;
        float sum = 0.0f;
        #pragma unroll
        for (int idx = lane; idx < FEAT; idx += 8)
            sum = fmaf(w[idx], s_feat[idx], sum);
        sum += __shfl_xor_sync(0xffffffffu, sum, 4);
        sum += __shfl_xor_sync(0xffffffffu, sum, 2);
        sum += __shfl_xor_sync(0xffffffffu, sum, 1);
        if (lane == 0 && row_raw < H1) s_h1[row] = tanhf(sum + b1[row]);
    }
    __syncthreads();

    // ---- Stage 4: h2 = tanh(W2 @ h1 + b2)   (10 outputs, one warp each; warps 0..9)
    if (t < H2 * 32) {
        const int row = t >> 5;
        const int lane = t & 31;
        const float* w = W2 + row * H1;
        float sum = 0.0f;
        for (int idx = lane; idx < H1; idx += 32)
            sum = fmaf(w[idx], s_h1[idx], sum);
        #pragma unroll
        for (int m = 16; m > 0; m >>= 1)
            sum += __shfl_xor_sync(0xffffffffu, sum, m);
        if (lane == 0) s_h2[row] = tanhf(sum + b2[row]);
    }
    __syncthreads();

    // ---- Stage 5: out = tanh(W3 @ h2 + b3)   (single full warp)
    if (t < 32) {
        float sum = (t < H2) ? W3[t] * s_h2[t] : 0.0f;
        #pragma unroll
        for (int m = 16; m > 0; m >>= 1)
            sum += __shfl_xor_sync(0xffffffffu, sum, m);
        if (t == 0) out[0] = tanhf(sum + b3[0]);
    }
}

extern "C" void kernel_launch(void* const* d_in, const int* in_sizes, int n_in,
                              void* d_out, int out_size) {
    (void)in_sizes; (void)n_in; (void)out_size;
    const float* x    = (const float*)d_in[0];
    const float* h0   = (const float*)d_in[1];
    const float* c0   = (const float*)d_in[2];
    const float* W_ih = (const float*)d_in[3];
    const float* W_hh = (const float*)d_in[4];
    const float* b_ih = (const float*)d_in[5];
    const float* b_hh = (const float*)d_in[6];
    const float* W1   = (const float*)d_in[7];
    const float* b1   = (const float*)d_in[8];
    const float* W2   = (const float*)d_in[9];
    const float* b2   = (const float*)d_in[10];
    const float* W3   = (const float*)d_in[11];
    const float* b3   = (const float*)d_in[12];
    float* out = (float*)d_out;

    lstm_mlp_fused<<<1, 800>>>(x, h0, c0, W_ih, W_hh, b_ih, b_hh,
                               W1, b1, W2, b2, W3, b3, out);
}